// round 9
// baseline (speedup 1.0000x reference)
#include <cuda_runtime.h>
#include <cuda_bf16.h>
#include <mma.h>
#include <math.h>
#include <stdint.h>

using namespace nvcuda;

constexpr int SEQ   = 2048;
constexpr int HIDN  = 2048;
constexpr int NHEAD = 16;
constexpr int DHEAD = 128;
constexpr int QKVO  = 6144;
constexpr int KOFF  = 2048;
constexpr int VOFF  = 4096;

constexpr int BK   = 32;
constexpr int AKP  = 48;   // 96 B row stride (32B multiple)
constexpr int BNPb = 144;  // 288 B row stride

__device__ float g_qkv_r[(size_t)SEQ * QKVO];
__device__ float g_qkv_i[(size_t)SEQ * QKVO];
__device__ float g_scores[(size_t)NHEAD * SEQ * SEQ];
__device__ float g_attn_r[(size_t)SEQ * HIDN];
__device__ float g_attn_i[(size_t)SEQ * HIDN];
__device__ float g_cos[SEQ * DHEAD];
__device__ float g_sin[SEQ * DHEAD];

using AFrag  = wmma::fragment<wmma::matrix_a, 16, 16, 16, __nv_bfloat16, wmma::row_major>;
using BFragR = wmma::fragment<wmma::matrix_b, 16, 16, 16, __nv_bfloat16, wmma::row_major>;
using BFragC = wmma::fragment<wmma::matrix_b, 16, 16, 16, __nv_bfloat16, wmma::col_major>;
using CFrag  = wmma::fragment<wmma::accumulator, 16, 16, 16, float>;

__device__ __forceinline__ void ld_128x32(float4 r[4], const float* g, int ld) {
    int t = threadIdx.x;
#pragma unroll
    for (int i = 0; i < 4; i++) {
        int f = t + i * 256;
        int row = f >> 3, col = (f & 7) << 2;
        r[i] = *reinterpret_cast<const float4*>(g + (size_t)row * ld + col);
    }
}
__device__ __forceinline__ void ld_32x128(float4 r[4], const float* g, int ld) {
    int t = threadIdx.x;
#pragma unroll
    for (int i = 0; i < 4; i++) {
        int f = t + i * 256;
        int row = f >> 5, col = (f & 31) << 2;
        r[i] = *reinterpret_cast<const float4*>(g + (size_t)row * ld + col);
    }
}

__device__ __forceinline__ void split_st4(__nv_bfloat16* hi, __nv_bfloat16* lo,
                                          int off, float4 v) {
    float x[4] = {v.x, v.y, v.z, v.w};
    __nv_bfloat16 h[4], l[4];
#pragma unroll
    for (int j = 0; j < 4; j++) {
        h[j] = __float2bfloat16_rn(x[j]);
        l[j] = __float2bfloat16_rn(x[j] - __bfloat162float(h[j]));
    }
    *reinterpret_cast<__nv_bfloat162*>(hi + off)     = __halves2bfloat162(h[0], h[1]);
    *reinterpret_cast<__nv_bfloat162*>(hi + off + 2) = __halves2bfloat162(h[2], h[3]);
    *reinterpret_cast<__nv_bfloat162*>(lo + off)     = __halves2bfloat162(l[0], l[1]);
    *reinterpret_cast<__nv_bfloat162*>(lo + off + 2) = __halves2bfloat162(l[2], l[3]);
}
__device__ __forceinline__ void st_128x32s(const float4 r[4], __nv_bfloat16* hi, __nv_bfloat16* lo) {
    int t = threadIdx.x;
#pragma unroll
    for (int i = 0; i < 4; i++) {
        int f = t + i * 256;
        int row = f >> 3, col = (f & 7) << 2;
        split_st4(hi, lo, row * AKP + col, r[i]);
    }
}
__device__ __forceinline__ void st_32x128s(const float4 r[4], __nv_bfloat16* hi, __nv_bfloat16* lo) {
    int t = threadIdx.x;
#pragma unroll
    for (int i = 0; i < 4; i++) {
        int f = t + i * 256;
        int row = f >> 5, col = (f & 31) << 2;
        split_st4(hi, lo, row * BNPb + col, r[i]);
    }
}

template <bool BT>
__device__ __forceinline__ void mma_bf16(const __nv_bfloat16* Ah, const __nv_bfloat16* Al,
                                         const __nv_bfloat16* Bh, const __nv_bfloat16* Bl,
                                         CFrag acc[4][2], int wm, int wn) {
#pragma unroll
    for (int kk = 0; kk < BK; kk += 16) {
        AFrag ah[4], al[4];
#pragma unroll
        for (int mi = 0; mi < 4; mi++) {
            wmma::load_matrix_sync(ah[mi], Ah + (wm * 64 + mi * 16) * AKP + kk, AKP);
            wmma::load_matrix_sync(al[mi], Al + (wm * 64 + mi * 16) * AKP + kk, AKP);
        }
#pragma unroll
        for (int ni = 0; ni < 2; ni++) {
            if constexpr (BT) {
                BFragC bh, bl;
                wmma::load_matrix_sync(bh, Bh + (wn * 32 + ni * 16) * AKP + kk, AKP);
                wmma::load_matrix_sync(bl, Bl + (wn * 32 + ni * 16) * AKP + kk, AKP);
#pragma unroll
                for (int mi = 0; mi < 4; mi++) {
                    wmma::mma_sync(acc[mi][ni], ah[mi], bh, acc[mi][ni]);
                    wmma::mma_sync(acc[mi][ni], al[mi], bh, acc[mi][ni]);
                    wmma::mma_sync(acc[mi][ni], ah[mi], bl, acc[mi][ni]);
                }
            } else {
                BFragR bh, bl;
                wmma::load_matrix_sync(bh, Bh + kk * BNPb + wn * 32 + ni * 16, BNPb);
                wmma::load_matrix_sync(bl, Bl + kk * BNPb + wn * 32 + ni * 16, BNPb);
#pragma unroll
                for (int mi = 0; mi < 4; mi++) {
                    wmma::mma_sync(acc[mi][ni], ah[mi], bh, acc[mi][ni]);
                    wmma::mma_sync(acc[mi][ni], al[mi], bh, acc[mi][ni]);
                    wmma::mma_sync(acc[mi][ni], ah[mi], bl, acc[mi][ni]);
                }
            }
        }
    }
}

__device__ __forceinline__ void epi_direct(CFrag acc[4][2], float* Cb, int ldc, int wm, int wn) {
#pragma unroll
    for (int mi = 0; mi < 4; mi++)
#pragma unroll
        for (int ni = 0; ni < 2; ni++)
            wmma::store_matrix_sync(Cb + (size_t)(wm * 64 + mi * 16) * ldc + wn * 32 + ni * 16,
                                    acc[mi][ni], ldc, wmma::mem_row_major);
}

// kernel 1: dual QKV raw GEMM
__global__ void __launch_bounds__(256)
k_qkv(const float* __restrict__ X, const float* __restrict__ Wr, const float* __restrict__ Wi) {
    __shared__ alignas(128) __nv_bfloat16 Ah[128 * AKP], Al[128 * AKP];
    __shared__ alignas(128) __nv_bfloat16 Bh[32 * BNPb], Bl[32 * BNPb];
    const float* W = blockIdx.z ? Wi : Wr;
    float* C       = blockIdx.z ? g_qkv_i : g_qkv_r;
    int i0 = blockIdx.y * 128, n0 = blockIdx.x * 128;
    int warp = threadIdx.x >> 5, wm = warp >> 2, wn = warp & 3;
    CFrag acc[4][2];
#pragma unroll
    for (int mi = 0; mi < 4; mi++)
#pragma unroll
        for (int ni = 0; ni < 2; ni++) wmma::fill_fragment(acc[mi][ni], 0.0f);

    const float* Ag = X + (size_t)i0 * HIDN;
    const float* Bg = W + n0;
    float4 ra[4], rb[4];
    ld_128x32(ra, Ag, HIDN);
    ld_32x128(rb, Bg, QKVO);
    const int kts = HIDN / BK;
    for (int kt = 0; kt < kts; ++kt) {
        st_128x32s(ra, Ah, Al);
        st_32x128s(rb, Bh, Bl);
        __syncthreads();
        if (kt + 1 < kts) {
            ld_128x32(ra, Ag + (kt + 1) * BK, HIDN);
            ld_32x128(rb, Bg + (size_t)(kt + 1) * BK * QKVO, QKVO);
        }
        mma_bf16<false>(Ah, Al, Bh, Bl, acc, wm, wn);
        __syncthreads();
    }
    epi_direct(acc, C + (size_t)i0 * QKVO + n0, QKVO, wm, wn);
}

// kernel 2a: RoPE trig tables (fp64 angles)
__global__ void k_trig(const int* __restrict__ pos) {
    int idx = blockIdx.x * 256 + threadIdx.x;
    int s = idx >> 7, d = idx & 127;
    double invf = exp(-(double)d * (13.815510557964274 / 128.0));
    double th = (double)pos[s] * invf;
    double c, sn;
    sincos(th, &c, &sn);
    g_cos[idx] = (float)c;
    g_sin[idx] = (float)sn;
}

// kernel 2b: bias + complex rotation by MINUS theta (q,k), bias only (v).
// Hypothesis: executed reference uses the opposite rotation convention:
//   x_r' = x_r*cos + x_i*sin ;  x_i' = -x_r*sin + x_i*cos   (rotation by -theta)
__global__ void k_biasrope(const float* __restrict__ br, const float* __restrict__ bi) {
    int idx = blockIdx.x * 256 + threadIdx.x;
    int s = idx / QKVO;
    int c = idx - s * QKVO;
    size_t o = (size_t)s * QKVO + c;
    float xr = g_qkv_r[o] + br[c];
    float xi = g_qkv_i[o] + bi[c];
    if (c < VOFF) {
        int ti = (s << 7) | (c & 127);
        float cf = g_cos[ti], sf = g_sin[ti];
        float nr = xr * cf + xi * sf;     // sign-flipped rotation
        float ni = -xr * sf + xi * cf;
        xr = nr; xi = ni;
    }
    g_qkv_r[o] = xr;
    g_qkv_i[o] = xi;
}

// kernel 3: raw scores = qr.kr + qi.ki (NT, K=256)
__global__ void __launch_bounds__(256)
k_scores() {
    int h = blockIdx.z, i0 = blockIdx.y * 128, j0 = blockIdx.x * 128;
    if (j0 > i0) return;
    __shared__ alignas(128) __nv_bfloat16 Ah[128 * AKP], Al[128 * AKP];
    __shared__ alignas(128) __nv_bfloat16 Bh[128 * AKP], Bl[128 * AKP];
    int warp = threadIdx.x >> 5, wm = warp >> 2, wn = warp & 3;
    CFrag acc[4][2];
#pragma unroll
    for (int mi = 0; mi < 4; mi++)
#pragma unroll
        for (int ni = 0; ni < 2; ni++) wmma::fill_fragment(acc[mi][ni], 0.0f);

    float4 ra[4], rb[4];
    ld_128x32(ra, g_qkv_r + (size_t)i0 * QKVO + h * DHEAD, QKVO);
    ld_128x32(rb, g_qkv_r + (size_t)j0 * QKVO + KOFF + h * DHEAD, QKVO);
    for (int kt = 0; kt < 8; ++kt) {
        st_128x32s(ra, Ah, Al);
        st_128x32s(rb, Bh, Bl);
        __syncthreads();
        if (kt + 1 < 8) {
            int nk = kt + 1;
            const float* buf = (nk >= 4) ? g_qkv_i : g_qkv_r;
            int kc = (nk & 3) * BK;
            ld_128x32(ra, buf + (size_t)i0 * QKVO + h * DHEAD + kc, QKVO);
            ld_128x32(rb, buf + (size_t)j0 * QKVO + KOFF + h * DHEAD + kc, QKVO);
        }
        mma_bf16<true>(Ah, Al, Bh, Bl, acc, wm, wn);
        __syncthreads();
    }
    epi_direct(acc, g_scores + ((size_t)h * SEQ + i0) * SEQ + j0, SEQ, wm, wn);
}

// kernel 4: scale + causal mask + softmax (in place)
__global__ void __launch_bounds__(256)
k_softmax() {
    int bx = blockIdx.x;
    int r = bx & (SEQ - 1);
    float* p = g_scores + (size_t)bx * SEQ;
    int tid = threadIdx.x;
    float4* pv = reinterpret_cast<float4*>(p);
    float4 v0 = pv[tid];
    float4 v1 = pv[tid + 256];
    const float scale = 0.08838834764831845f;
    float a[8] = {v0.x, v0.y, v0.z, v0.w, v1.x, v1.y, v1.z, v1.w};
    int c0 = tid * 4, c1 = 1024 + tid * 4;
    int cols[8] = {c0, c0 + 1, c0 + 2, c0 + 3, c1, c1 + 1, c1 + 2, c1 + 3};

    float m = -3.4e38f;
#pragma unroll
    for (int j = 0; j < 8; j++)
        if (cols[j] <= r) { a[j] *= scale; m = fmaxf(m, a[j]); }

    __shared__ float red[8];
#pragma unroll
    for (int o = 16; o; o >>= 1) m = fmaxf(m, __shfl_xor_sync(0xffffffffu, m, o));
    if ((tid & 31) == 0) red[tid >> 5] = m;
    __syncthreads();
    float mb = fmaxf(fmaxf(fmaxf(red[0], red[1]), fmaxf(red[2], red[3])),
                     fmaxf(fmaxf(red[4], red[5]), fmaxf(red[6], red[7])));

    float s = 0.f;
#pragma unroll
    for (int j = 0; j < 8; j++) {
        a[j] = (cols[j] <= r) ? expf(a[j] - mb) : 0.f;
        s += a[j];
    }
#pragma unroll
    for (int o = 16; o; o >>= 1) s += __shfl_xor_sync(0xffffffffu, s, o);
    __syncthreads();
    if ((tid & 31) == 0) red[tid >> 5] = s;
    __syncthreads();
    float inv = 1.0f / (red[0] + red[1] + red[2] + red[3] + red[4] + red[5] + red[6] + red[7]);

    v0 = make_float4(a[0] * inv, a[1] * inv, a[2] * inv, a[3] * inv);
    v1 = make_float4(a[4] * inv, a[5] * inv, a[6] * inv, a[7] * inv);
    pv[tid] = v0;
    pv[tid + 256] = v1;
}

// kernel 5: attn @ V
__global__ void __launch_bounds__(256)
k_av() {
    int bz = blockIdx.z;
    int h = bz >> 1, pz = bz & 1;
    int i0 = blockIdx.y * 128;
    const float* Pm = g_scores + (size_t)h * SEQ * SEQ + (size_t)i0 * SEQ;
    const float* V  = (pz ? g_qkv_i : g_qkv_r) + VOFF + h * DHEAD;
    float* C        = (pz ? g_attn_i : g_attn_r) + (size_t)i0 * HIDN + h * DHEAD;

    __shared__ alignas(128) __nv_bfloat16 Ah[128 * AKP], Al[128 * AKP];
    __shared__ alignas(128) __nv_bfloat16 Bh[32 * BNPb], Bl[32 * BNPb];
    int warp = threadIdx.x >> 5, wm = warp >> 2, wn = warp & 3;
    CFrag acc[4][2];
#pragma unroll
    for (int mi = 0; mi < 4; mi++)
#pragma unroll
        for (int ni = 0; ni < 2; ni++) wmma::fill_fragment(acc[mi][ni], 0.0f);

    int ktiles = (i0 + 128) / BK;
    float4 ra[4], rb[4];
    ld_128x32(ra, Pm, SEQ);
    ld_32x128(rb, V, QKVO);
    for (int kt = 0; kt < ktiles; ++kt) {
        st_128x32s(ra, Ah, Al);
        st_32x128s(rb, Bh, Bl);
        __syncthreads();
        if (kt + 1 < ktiles) {
            ld_128x32(ra, Pm + (kt + 1) * BK, SEQ);
            ld_32x128(rb, V + (size_t)(kt + 1) * BK * QKVO, QKVO);
        }
        mma_bf16<false>(Ah, Al, Bh, Bl, acc, wm, wn);
        __syncthreads();
    }
    epi_direct(acc, C, HIDN, wm, wn);
}

// kernel 6: output projections
__global__ void __launch_bounds__(256)
k_out(const float* __restrict__ Wor, const float* __restrict__ Woi, float* __restrict__ out) {
    int z = blockIdx.z;
    const float* A = z ? g_attn_i : g_attn_r;
    const float* W = z ? Woi : Wor;
    float* C = out + (size_t)z * SEQ * HIDN;
    int i0 = blockIdx.y * 128, n0 = blockIdx.x * 128;

    __shared__ alignas(128) __nv_bfloat16 Ah[128 * AKP], Al[128 * AKP];
    __shared__ alignas(128) __nv_bfloat16 Bh[32 * BNPb], Bl[32 * BNPb];
    int warp = threadIdx.x >> 5, wm = warp >> 2, wn = warp & 3;
    CFrag acc[4][2];
#pragma unroll
    for (int mi = 0; mi < 4; mi++)
#pragma unroll
        for (int ni = 0; ni < 2; ni++) wmma::fill_fragment(acc[mi][ni], 0.0f);

    const float* Ag = A + (size_t)i0 * HIDN;
    const float* Bg = W + n0;
    float4 ra[4], rb[4];
    ld_128x32(ra, Ag, HIDN);
    ld_32x128(rb, Bg, HIDN);
    const int kts = HIDN / BK;
    for (int kt = 0; kt < kts; ++kt) {
        st_128x32s(ra, Ah, Al);
        st_32x128s(rb, Bh, Bl);
        __syncthreads();
        if (kt + 1 < kts) {
            ld_128x32(ra, Ag + (kt + 1) * BK, HIDN);
            ld_32x128(rb, Bg + (size_t)(kt + 1) * BK * HIDN, HIDN);
        }
        mma_bf16<false>(Ah, Al, Bh, Bl, acc, wm, wn);
        __syncthreads();
    }
    epi_direct(acc, C + (size_t)i0 * HIDN + n0, HIDN, wm, wn);
}

extern "C" void kernel_launch(void* const* d_in, const int* in_sizes, int n_in,
                              void* d_out, int out_size) {
    const float* hidden = (const float*)d_in[0];
    const int*   pos    = (const int*)d_in[1];
    const float* Wqkv_r = (const float*)d_in[2];
    const float* Wqkv_i = (const float*)d_in[4];
    const float* bqkv_r = (const float*)d_in[3];
    const float* bqkv_i = (const float*)d_in[5];
    const float* Wo_r   = (const float*)d_in[6];
    const float* Wo_i   = (const float*)d_in[7];
    float* out = (float*)d_out;

    dim3 blk(256);
    k_trig<<<(SEQ * DHEAD) / 256, blk>>>(pos);
    k_qkv<<<dim3(QKVO / 128, SEQ / 128, 2), blk>>>(hidden, Wqkv_r, Wqkv_i);
    k_biasrope<<<(SEQ * QKVO) / 256, blk>>>(bqkv_r, bqkv_i);
    k_scores<<<dim3(SEQ / 128, SEQ / 128, NHEAD), blk>>>();
    k_softmax<<<NHEAD * SEQ, blk>>>();
    k_av<<<dim3(1, SEQ / 128, NHEAD * 2), blk>>>();
    int zcount = (out_size >= 2 * SEQ * HIDN) ? 2 : 1;
    k_out<<<dim3(HIDN / 128, SEQ / 128, zcount), blk>>>(Wo_r, Wo_i, out);
}